// round 5
// baseline (speedup 1.0000x reference)
#include <cuda_runtime.h>

#define NB   64          // number of 64-row blocks along sequence
#define SEQL 4096
#define DIM  64
#define NEG  (-10000.0f)

#define PQ 65            // pitch (floats) for Qs and Ps
#define PK 65            // pitch for Ks
#define PVV 64           // pitch for Vs

// Shared layout (dynamic): Qs[64*PQ] | Ks[64*PK] | Vs[64*PVV] | Ps[64*PQ]
#define SMEM_FLOATS (64*PQ + 64*PK + 64*PVV + 64*PQ)
#define SMEM_BYTES  (SMEM_FLOATS * 4)

__global__ __launch_bounds__(128, 3)
void bb_attn_kernel(const float*  __restrict__ Q,
                    const float*  __restrict__ K,
                    const float*  __restrict__ V,
                    const int*    __restrict__ rand_attn,
                    const float*  __restrict__ from_mask,
                    const float*  __restrict__ to_mask,
                    const float*  __restrict__ rand_mask,
                    const float*  __restrict__ band_mask,
                    float*        __restrict__ out)
{
    extern __shared__ float sm[];
    float* Qs = sm;
    float* Ks = Qs + 64 * PQ;
    float* Vs = Ks + 64 * PK;
    float* Ps = Vs + 64 * PVV;

    const int i   = blockIdx.x & (NB - 1);   // q-block index
    const int bh  = blockIdx.x >> 6;         // b*16 + h
    const int b   = bh >> 4;
    const int tid = threadIdx.x;             // 128 threads
    const int jg  = tid & 7;                 // key/col group (stride-8)
    const int qg  = tid >> 3;                // 0..15
    const int q0  = qg << 2;                 // 4 q-rows per thread

    // ---- Load Q block into shared (pitch 65, scalar stores) ----
    const float* Qg = Q + ((size_t)bh * SEQL + (size_t)i * 64) * DIM;
    for (int f = tid; f < 1024; f += 128) {
        int row = f >> 4, c4 = (f & 15) << 2;
        float4 t4 = __ldg((const float4*)(Qg + row * DIM + c4));
        float* dst = Qs + row * PQ + c4;
        dst[0] = t4.x; dst[1] = t4.y; dst[2] = t4.z; dst[3] = t4.w;
    }

    // ---- Build key-block list ----
    // mt: 0 = to_mask (col-only), 1 = band_mask (mp = window slot 0..2),
    //     2 = rand_mask (mp = random slot 0..2)
    const bool full = (i == 0 || i == NB - 1);
    int nt;
    int kbl[8], mtl[8], mpl[8];
    if (full) {
        nt = NB;
    } else {
        const int* ra = rand_attn + ((size_t)bh * (NB - 2) + (i - 1)) * 3;
        int r0 = __ldg(ra + 0), r1 = __ldg(ra + 1), r2 = __ldg(ra + 2);
        if (i == 1) {
            kbl[0] = 0;  kbl[1] = 1;  kbl[2] = 2;  kbl[3] = NB - 1;
            mtl[0] = mtl[1] = mtl[2] = mtl[3] = 0;
            mpl[0] = mpl[1] = mpl[2] = mpl[3] = 0;
            kbl[4] = r0; kbl[5] = r1; kbl[6] = r2;
            mtl[4] = mtl[5] = mtl[6] = 2;
            mpl[4] = 0; mpl[5] = 1; mpl[6] = 2;
            nt = 7;
        } else if (i == NB - 2) {
            kbl[0] = 0;  kbl[1] = NB - 3; kbl[2] = NB - 2; kbl[3] = NB - 1;
            mtl[0] = mtl[1] = mtl[2] = mtl[3] = 0;
            mpl[0] = mpl[1] = mpl[2] = mpl[3] = 0;
            kbl[4] = r0; kbl[5] = r1; kbl[6] = r2;
            mtl[4] = mtl[5] = mtl[6] = 2;
            mpl[4] = 0; mpl[5] = 1; mpl[6] = 2;
            nt = 7;
        } else {
            kbl[0] = 0;     mtl[0] = 0; mpl[0] = 0;
            kbl[1] = i - 1; mtl[1] = 1; mpl[1] = 0;
            kbl[2] = i;     mtl[2] = 1; mpl[2] = 1;
            kbl[3] = i + 1; mtl[3] = 1; mpl[3] = 2;
            kbl[4] = r0;    mtl[4] = 2; mpl[4] = 0;
            kbl[5] = r1;    mtl[5] = 2; mpl[5] = 1;
            kbl[6] = r2;    mtl[6] = 2; mpl[6] = 2;
            kbl[7] = NB - 1; mtl[7] = 0; mpl[7] = 0;
            nt = 8;
        }
    }

    // ---- Online-softmax state ----
    float acc[4][8];
    float mrow[4], lrow[4];
    #pragma unroll
    for (int r = 0; r < 4; r++) {
        mrow[r] = -1e30f; lrow[r] = 0.0f;
        #pragma unroll
        for (int c = 0; c < 8; c++) acc[r][c] = 0.0f;
    }

    const float SC = 0.125f;  // 1/sqrt(64)

    for (int t = 0; t < nt; t++) {
        int kb, mt, mp;
        if (full) { kb = t; mt = 0; mp = 0; }
        else      { kb = kbl[t]; mt = mtl[t]; mp = mpl[t]; }

        __syncthreads();   // prev PV done reading Vs/Ps; Qs ready on t==0

        // ---- Load K, V block into shared ----
        const float* Kg = K + ((size_t)bh * SEQL + (size_t)kb * 64) * DIM;
        const float* Vg = V + ((size_t)bh * SEQL + (size_t)kb * 64) * DIM;
        for (int f = tid; f < 1024; f += 128) {
            int row = f >> 4, c4 = (f & 15) << 2;
            float4 kk = __ldg((const float4*)(Kg + row * DIM + c4));
            float* kd = Ks + row * PK + c4;
            kd[0] = kk.x; kd[1] = kk.y; kd[2] = kk.z; kd[3] = kk.w;
            float4 vv = __ldg((const float4*)(Vg + row * DIM + c4));
            *(float4*)(Vs + row * PVV + c4) = vv;
        }
        __syncthreads();

        // ---- QK^T: 4x8 tile per thread ----
        float s[4][8];
        #pragma unroll
        for (int r = 0; r < 4; r++)
            #pragma unroll
            for (int c = 0; c < 8; c++) s[r][c] = 0.0f;

        #pragma unroll 8
        for (int d = 0; d < DIM; d++) {
            float qv[4], kv[8];
            #pragma unroll
            for (int r = 0; r < 4; r++) qv[r] = Qs[(q0 + r) * PQ + d];
            #pragma unroll
            for (int c = 0; c < 8; c++) kv[c] = Ks[(jg + (c << 3)) * PK + d];
            #pragma unroll
            for (int r = 0; r < 4; r++)
                #pragma unroll
                for (int c = 0; c < 8; c++)
                    s[r][c] = fmaf(qv[r], kv[c], s[r][c]);
        }

        // ---- scale + mask ----
        if (mt == 0) {
            const float* tmp = to_mask + (size_t)b * SEQL + (size_t)kb * 64 + jg;
            float tadd[8];
            #pragma unroll
            for (int c = 0; c < 8; c++)
                tadd[c] = (1.0f - __ldg(tmp + (c << 3))) * NEG;
            #pragma unroll
            for (int r = 0; r < 4; r++)
                #pragma unroll
                for (int c = 0; c < 8; c++)
                    s[r][c] = s[r][c] * SC + tadd[c];
        } else if (mt == 1) {
            // band_mask: (B,1,NB-4,64,192); window slot mp in {0,1,2}
            const float* bm = band_mask
                + (((size_t)b * (NB - 4) + (i - 2)) * 64) * 192 + mp * 64 + jg;
            #pragma unroll
            for (int r = 0; r < 4; r++) {
                const float* bmr = bm + (size_t)(q0 + r) * 192;
                #pragma unroll
                for (int c = 0; c < 8; c++)
                    s[r][c] = s[r][c] * SC + (1.0f - __ldg(bmr + (c << 3))) * NEG;
            }
        } else {
            // rand_mask: (B,H,NB-2,64,192); rand window = i-1, slot mp
            const float* rm = rand_mask
                + (((size_t)bh * (NB - 2) + (i - 1)) * 64) * 192 + mp * 64 + jg;
            #pragma unroll
            for (int r = 0; r < 4; r++) {
                const float* rmr = rm + (size_t)(q0 + r) * 192;
                #pragma unroll
                for (int c = 0; c < 8; c++)
                    s[r][c] = s[r][c] * SC + (1.0f - __ldg(rmr + (c << 3))) * NEG;
            }
        }

        // ---- online softmax (row groups = 8 consecutive lanes) ----
        #pragma unroll
        for (int r = 0; r < 4; r++) {
            float mx = s[r][0];
            #pragma unroll
            for (int c = 1; c < 8; c++) mx = fmaxf(mx, s[r][c]);
            mx = fmaxf(mx, __shfl_xor_sync(0xffffffffu, mx, 1));
            mx = fmaxf(mx, __shfl_xor_sync(0xffffffffu, mx, 2));
            mx = fmaxf(mx, __shfl_xor_sync(0xffffffffu, mx, 4));
            float mnew = fmaxf(mrow[r], mx);
            float corr = __expf(mrow[r] - mnew);
            float ls = 0.0f;
            #pragma unroll
            for (int c = 0; c < 8; c++) {
                float p = __expf(s[r][c] - mnew);
                s[r][c] = p;
                ls += p;
            }
            ls += __shfl_xor_sync(0xffffffffu, ls, 1);
            ls += __shfl_xor_sync(0xffffffffu, ls, 2);
            ls += __shfl_xor_sync(0xffffffffu, ls, 4);
            lrow[r] = lrow[r] * corr + ls;
            mrow[r] = mnew;
            #pragma unroll
            for (int c = 0; c < 8; c++) acc[r][c] *= corr;
            // stage P to shared for the PV stage
            #pragma unroll
            for (int c = 0; c < 8; c++)
                Ps[(q0 + r) * PQ + jg + (c << 3)] = s[r][c];
        }
        __syncthreads();

        // ---- PV: acc[4][8] over 64 keys ----
        #pragma unroll 8
        for (int j = 0; j < 64; j++) {
            float pv[4], vv[8];
            #pragma unroll
            for (int r = 0; r < 4; r++) pv[r] = Ps[(q0 + r) * PQ + j];
            #pragma unroll
            for (int c = 0; c < 8; c++) vv[c] = Vs[j * PVV + jg + (c << 3)];
            #pragma unroll
            for (int r = 0; r < 4; r++)
                #pragma unroll
                for (int c = 0; c < 8; c++)
                    acc[r][c] = fmaf(pv[r], vv[c], acc[r][c]);
        }
    }

    // ---- epilogue: normalize, from_mask, store ----
    float* og = out + ((size_t)bh * SEQL + (size_t)i * 64) * DIM;
    #pragma unroll
    for (int r = 0; r < 4; r++) {
        float fm = __ldg(from_mask + (size_t)b * SEQL + (size_t)i * 64 + q0 + r);
        float inv = fm / lrow[r];
        #pragma unroll
        for (int c = 0; c < 8; c++)
            og[(q0 + r) * DIM + jg + (c << 3)] = acc[r][c] * inv;
    }
}

extern "C" void kernel_launch(void* const* d_in, const int* in_sizes, int n_in,
                              void* d_out, int out_size)
{
    const float* Q  = (const float*)d_in[0];
    const float* K  = (const float*)d_in[1];
    const float* V  = (const float*)d_in[2];
    const int*   RA = (const int*)  d_in[3];
    const float* FM = (const float*)d_in[4];
    const float* TM = (const float*)d_in[5];
    const float* RM = (const float*)d_in[6];
    const float* BM = (const float*)d_in[7];
    float* O = (float*)d_out;

    cudaFuncSetAttribute(bb_attn_kernel,
                         cudaFuncAttributeMaxDynamicSharedMemorySize, SMEM_BYTES);

    dim3 grid(2 * 16 * NB);   // one CTA per (b,h,q-block)
    bb_attn_kernel<<<grid, 128, SMEM_BYTES>>>(Q, K, V, RA, FM, TM, RM, BM, O);
}

// round 6
// speedup vs baseline: 1.6401x; 1.6401x over previous
#include <cuda_runtime.h>

#define NB   64
#define SEQL 4096
#define DIM  64
#define NEG  (-10000.0f)

#define PQ 68            // pitch (floats) Qs / Ps  (mult of 4, 4*68 mod 128 = 16)
#define PK 68            // pitch Ks
#define PVV 64           // pitch Vs (row-major V)

#define QS_OFF 0
#define KS_OFF (64*PQ)
#define VS_OFF (KS_OFF + 64*PK)
#define PS_OFF (VS_OFF + 64*PVV)
#define SMEM_FLOATS (PS_OFF + 64*PQ)
#define SMEM_BYTES  (SMEM_FLOATS * 4)

__global__ __launch_bounds__(128, 3)
void bb_attn_kernel(const float*  __restrict__ Q,
                    const float*  __restrict__ K,
                    const float*  __restrict__ V,
                    const int*    __restrict__ rand_attn,
                    const float*  __restrict__ from_mask,
                    const float*  __restrict__ to_mask,
                    const float*  __restrict__ rand_mask,
                    const float*  __restrict__ band_mask,
                    float*        __restrict__ out)
{
    extern __shared__ float sm[];
    float* Qs = sm + QS_OFF;
    float* Ks = sm + KS_OFF;
    float* Vs = sm + VS_OFF;
    float* Ps = sm + PS_OFF;

    // ---- heavy-first block remap: full-attention blocks (i=0, NB-1) go first ----
    int i, bh;
    {
        int bid = blockIdx.x;
        if (bid < 64) { bh = bid >> 1; i = (bid & 1) ? (NB - 1) : 0; }
        else          { int x = bid - 64; bh = x / 62; i = 1 + (x - bh * 62); }
    }
    const int b   = bh >> 4;
    const int tid = threadIdx.x;
    const int jg  = tid & 7;        // lane group 0..7
    const int qg  = tid >> 3;       // 0..15
    const int q0  = qg << 2;        // 4 q-rows per thread

    // ---- Load Q block into shared (float4 stores, pitch 68) ----
    const float* Qg = Q + ((size_t)bh * SEQL + (size_t)i * 64) * DIM;
    for (int f = tid; f < 1024; f += 128) {
        int row = f >> 4, c4 = (f & 15) << 2;
        float4 t4 = __ldg((const float4*)(Qg + row * DIM + c4));
        *(float4*)(Qs + row * PQ + c4) = t4;
    }

    // ---- Build key-block list ----
    const bool full = (i == 0 || i == NB - 1);
    int nt;
    int kbl[8], mtl[8], mpl[8];
    if (full) {
        nt = NB;
    } else {
        const int* ra = rand_attn + ((size_t)bh * (NB - 2) + (i - 1)) * 3;
        int r0 = __ldg(ra + 0), r1 = __ldg(ra + 1), r2 = __ldg(ra + 2);
        if (i == 1) {
            kbl[0]=0; kbl[1]=1; kbl[2]=2; kbl[3]=NB-1;
            mtl[0]=mtl[1]=mtl[2]=mtl[3]=0; mpl[0]=mpl[1]=mpl[2]=mpl[3]=0;
            kbl[4]=r0; kbl[5]=r1; kbl[6]=r2;
            mtl[4]=mtl[5]=mtl[6]=2; mpl[4]=0; mpl[5]=1; mpl[6]=2;
            nt = 7;
        } else if (i == NB - 2) {
            kbl[0]=0; kbl[1]=NB-3; kbl[2]=NB-2; kbl[3]=NB-1;
            mtl[0]=mtl[1]=mtl[2]=mtl[3]=0; mpl[0]=mpl[1]=mpl[2]=mpl[3]=0;
            kbl[4]=r0; kbl[5]=r1; kbl[6]=r2;
            mtl[4]=mtl[5]=mtl[6]=2; mpl[4]=0; mpl[5]=1; mpl[6]=2;
            nt = 7;
        } else {
            kbl[0]=0;    mtl[0]=0; mpl[0]=0;
            kbl[1]=i-1;  mtl[1]=1; mpl[1]=0;
            kbl[2]=i;    mtl[2]=1; mpl[2]=1;
            kbl[3]=i+1;  mtl[3]=1; mpl[3]=2;
            kbl[4]=r0;   mtl[4]=2; mpl[4]=0;
            kbl[5]=r1;   mtl[5]=2; mpl[5]=1;
            kbl[6]=r2;   mtl[6]=2; mpl[6]=2;
            kbl[7]=NB-1; mtl[7]=0; mpl[7]=0;
            nt = 8;
        }
    }

    // ---- state: acc over output dims [4*jg,4*jg+4) and [32+4*jg, +4) ----
    float4 accA[4], accB[4];
    float mrow[4], lrow[4];
    #pragma unroll
    for (int r = 0; r < 4; r++) {
        mrow[r] = -1e30f; lrow[r] = 0.0f;
        accA[r] = make_float4(0.f,0.f,0.f,0.f);
        accB[r] = make_float4(0.f,0.f,0.f,0.f);
    }
    const float SC = 0.125f;

    for (int t = 0; t < nt; t++) {
        int kb, mt, mp;
        if (full) { kb = t; mt = 0; mp = 0; }
        else      { kb = kbl[t]; mt = mtl[t]; mp = mpl[t]; }

        __syncthreads();

        // ---- Load K, V block (float4) ----
        const float* Kg = K + ((size_t)bh * SEQL + (size_t)kb * 64) * DIM;
        const float* Vg = V + ((size_t)bh * SEQL + (size_t)kb * 64) * DIM;
        for (int f = tid; f < 1024; f += 128) {
            int row = f >> 4, c4 = (f & 15) << 2;
            float4 kk = __ldg((const float4*)(Kg + row * DIM + c4));
            *(float4*)(Ks + row * PK + c4) = kk;
            float4 vv = __ldg((const float4*)(Vg + row * DIM + c4));
            *(float4*)(Vs + row * PVV + c4) = vv;
        }
        __syncthreads();

        // ---- QK^T: 4x8 tile (keys owned: jg + 8c), vectorized over d ----
        float s[4][8];
        #pragma unroll
        for (int r = 0; r < 4; r++)
            #pragma unroll
            for (int c = 0; c < 8; c++) s[r][c] = 0.0f;

        #pragma unroll 4
        for (int d4 = 0; d4 < 16; d4++) {
            float4 qv[4], kv[8];
            #pragma unroll
            for (int r = 0; r < 4; r++)
                qv[r] = *(const float4*)(Qs + (q0 + r) * PQ + (d4 << 2));
            #pragma unroll
            for (int c = 0; c < 8; c++)
                kv[c] = *(const float4*)(Ks + (jg + (c << 3)) * PK + (d4 << 2));
            #pragma unroll
            for (int r = 0; r < 4; r++)
                #pragma unroll
                for (int c = 0; c < 8; c++) {
                    s[r][c] = fmaf(qv[r].x, kv[c].x, s[r][c]);
                    s[r][c] = fmaf(qv[r].y, kv[c].y, s[r][c]);
                    s[r][c] = fmaf(qv[r].z, kv[c].z, s[r][c]);
                    s[r][c] = fmaf(qv[r].w, kv[c].w, s[r][c]);
                }
        }

        // ---- scale + mask ----
        if (mt == 0) {
            const float* tmp = to_mask + (size_t)b * SEQL + (size_t)kb * 64 + jg;
            float tadd[8];
            #pragma unroll
            for (int c = 0; c < 8; c++)
                tadd[c] = (1.0f - __ldg(tmp + (c << 3))) * NEG;
            #pragma unroll
            for (int r = 0; r < 4; r++)
                #pragma unroll
                for (int c = 0; c < 8; c++)
                    s[r][c] = s[r][c] * SC + tadd[c];
        } else if (mt == 1) {
            const float* bm = band_mask
                + (((size_t)b * (NB - 4) + (i - 2)) * 64) * 192 + mp * 64 + jg;
            #pragma unroll
            for (int r = 0; r < 4; r++) {
                const float* bmr = bm + (size_t)(q0 + r) * 192;
                #pragma unroll
                for (int c = 0; c < 8; c++)
                    s[r][c] = s[r][c] * SC + (1.0f - __ldg(bmr + (c << 3))) * NEG;
            }
        } else {
            const float* rm = rand_mask
                + (((size_t)bh * (NB - 2) + (i - 1)) * 64) * 192 + mp * 64 + jg;
            #pragma unroll
            for (int r = 0; r < 4; r++) {
                const float* rmr = rm + (size_t)(q0 + r) * 192;
                #pragma unroll
                for (int c = 0; c < 8; c++)
                    s[r][c] = s[r][c] * SC + (1.0f - __ldg(rmr + (c << 3))) * NEG;
            }
        }

        // ---- online softmax (8-lane row groups) ----
        #pragma unroll
        for (int r = 0; r < 4; r++) {
            float mx = s[r][0];
            #pragma unroll
            for (int c = 1; c < 8; c++) mx = fmaxf(mx, s[r][c]);
            mx = fmaxf(mx, __shfl_xor_sync(0xffffffffu, mx, 1));
            mx = fmaxf(mx, __shfl_xor_sync(0xffffffffu, mx, 2));
            mx = fmaxf(mx, __shfl_xor_sync(0xffffffffu, mx, 4));
            float mnew = fmaxf(mrow[r], mx);
            float corr = __expf(mrow[r] - mnew);
            float ls = 0.0f;
            #pragma unroll
            for (int c = 0; c < 8; c++) {
                float p = __expf(s[r][c] - mnew);
                s[r][c] = p;
                ls += p;
            }
            ls += __shfl_xor_sync(0xffffffffu, ls, 1);
            ls += __shfl_xor_sync(0xffffffffu, ls, 2);
            ls += __shfl_xor_sync(0xffffffffu, ls, 4);
            lrow[r] = lrow[r] * corr + ls;
            mrow[r] = mnew;
            accA[r].x *= corr; accA[r].y *= corr; accA[r].z *= corr; accA[r].w *= corr;
            accB[r].x *= corr; accB[r].y *= corr; accB[r].z *= corr; accB[r].w *= corr;
            #pragma unroll
            for (int c = 0; c < 8; c++)
                Ps[(q0 + r) * PQ + jg + (c << 3)] = s[r][c];
        }
        __syncthreads();

        // ---- PV: dims owned [4jg,4jg+4) and [32+4jg,+4), vectorized over j ----
        #pragma unroll 4
        for (int j4 = 0; j4 < 16; j4++) {
            float4 pv[4];
            #pragma unroll
            for (int r = 0; r < 4; r++)
                pv[r] = *(const float4*)(Ps + (q0 + r) * PQ + (j4 << 2));
            float4 va[4], vb[4];
            #pragma unroll
            for (int jj = 0; jj < 4; jj++) {
                const float* vrow = Vs + ((j4 << 2) + jj) * PVV;
                va[jj] = *(const float4*)(vrow + (jg << 2));
                vb[jj] = *(const float4*)(vrow + 32 + (jg << 2));
            }
            #pragma unroll
            for (int r = 0; r < 4; r++) {
                float pr[4] = { pv[r].x, pv[r].y, pv[r].z, pv[r].w };
                #pragma unroll
                for (int jj = 0; jj < 4; jj++) {
                    accA[r].x = fmaf(pr[jj], va[jj].x, accA[r].x);
                    accA[r].y = fmaf(pr[jj], va[jj].y, accA[r].y);
                    accA[r].z = fmaf(pr[jj], va[jj].z, accA[r].z);
                    accA[r].w = fmaf(pr[jj], va[jj].w, accA[r].w);
                    accB[r].x = fmaf(pr[jj], vb[jj].x, accB[r].x);
                    accB[r].y = fmaf(pr[jj], vb[jj].y, accB[r].y);
                    accB[r].z = fmaf(pr[jj], vb[jj].z, accB[r].z);
                    accB[r].w = fmaf(pr[jj], vb[jj].w, accB[r].w);
                }
            }
        }
    }

    // ---- epilogue: normalize, from_mask, STG.128 ----
    float* og = out + ((size_t)bh * SEQL + (size_t)i * 64) * DIM;
    #pragma unroll
    for (int r = 0; r < 4; r++) {
        float fm = __ldg(from_mask + (size_t)b * SEQL + (size_t)i * 64 + q0 + r);
        float inv = fm / lrow[r];
        float4 oa = make_float4(accA[r].x*inv, accA[r].y*inv, accA[r].z*inv, accA[r].w*inv);
        float4 ob = make_float4(accB[r].x*inv, accB[r].y*inv, accB[r].z*inv, accB[r].w*inv);
        *(float4*)(og + (q0 + r) * DIM + (jg << 2))      = oa;
        *(float4*)(og + (q0 + r) * DIM + 32 + (jg << 2)) = ob;
    }
}

extern "C" void kernel_launch(void* const* d_in, const int* in_sizes, int n_in,
                              void* d_out, int out_size)
{
    const float* Q  = (const float*)d_in[0];
    const float* K  = (const float*)d_in[1];
    const float* V  = (const float*)d_in[2];
    const int*   RA = (const int*)  d_in[3];
    const float* FM = (const float*)d_in[4];
    const float* TM = (const float*)d_in[5];
    const float* RM = (const float*)d_in[6];
    const float* BM = (const float*)d_in[7];
    float* O = (float*)d_out;

    cudaFuncSetAttribute(bb_attn_kernel,
                         cudaFuncAttributeMaxDynamicSharedMemorySize, SMEM_BYTES);

    dim3 grid(2 * 16 * NB);
    bb_attn_kernel<<<grid, 128, SMEM_BYTES>>>(Q, K, V, RA, FM, TM, RM, BM, O);
}

// round 7
// speedup vs baseline: 1.6832x; 1.0263x over previous
#include <cuda_runtime.h>

#define NB   64
#define SEQL 4096
#define DIM  64
#define NEG  (-10000.0f)

#define PQ 68
#define PK 68
#define PVV 64

#define QS_OFF 0
#define KS_OFF (64*PQ)
#define VS_OFF (KS_OFF + 64*PK)
#define PS_OFF (VS_OFF + 64*PVV)
#define SMEM_FLOATS (PS_OFF + 64*PQ)
#define SMEM_BYTES  (SMEM_FLOATS * 4)

typedef unsigned long long u64;

__device__ __forceinline__ u64 ffma2(u64 a, u64 b, u64 c) {
    u64 d;
    asm("fma.rn.f32x2 %0, %1, %2, %3;" : "=l"(d) : "l"(a), "l"(b), "l"(c));
    return d;
}
__device__ __forceinline__ u64 fmul2(u64 a, u64 b) {
    u64 d;
    asm("mul.rn.f32x2 %0, %1, %2;" : "=l"(d) : "l"(a), "l"(b));
    return d;
}
__device__ __forceinline__ u64 splat2(float x) {
    u64 d; unsigned int u = __float_as_uint(x);
    asm("mov.b64 %0, {%1, %1};" : "=l"(d) : "r"(u));
    return d;
}
__device__ __forceinline__ float2 unpack2(u64 a) {
    unsigned int lo, hi;
    asm("mov.b64 {%0, %1}, %2;" : "=r"(lo), "=r"(hi) : "l"(a));
    return make_float2(__uint_as_float(lo), __uint_as_float(hi));
}

__global__ __launch_bounds__(128, 2)
void bb_attn_kernel(const float*  __restrict__ Q,
                    const float*  __restrict__ K,
                    const float*  __restrict__ V,
                    const int*    __restrict__ rand_attn,
                    const float*  __restrict__ from_mask,
                    const float*  __restrict__ to_mask,
                    const float*  __restrict__ rand_mask,
                    const float*  __restrict__ band_mask,
                    float*        __restrict__ out)
{
    extern __shared__ float sm[];
    float* Qs = sm + QS_OFF;
    float* Ks = sm + KS_OFF;
    float* Vs = sm + VS_OFF;
    float* Ps = sm + PS_OFF;

    // heavy-first remap: full-attention blocks first
    int i, bh;
    {
        int bid = blockIdx.x;
        if (bid < 64) { bh = bid >> 1; i = (bid & 1) ? (NB - 1) : 0; }
        else          { int x = bid - 64; bh = x / 62; i = 1 + (x - bh * 62); }
    }
    const int b   = bh >> 4;
    const int tid = threadIdx.x;
    const int jg  = tid & 7;
    const int qg  = tid >> 3;
    const int q0  = qg << 2;

    // ---- load Q (pre-scaled by 1/8, exact) ----
    const float* Qg = Q + ((size_t)bh * SEQL + (size_t)i * 64) * DIM;
    for (int f = tid; f < 1024; f += 128) {
        int row = f >> 4, c4 = (f & 15) << 2;
        float4 t4 = __ldg((const float4*)(Qg + row * DIM + c4));
        t4.x *= 0.125f; t4.y *= 0.125f; t4.z *= 0.125f; t4.w *= 0.125f;
        *(float4*)(Qs + row * PQ + c4) = t4;
    }

    // ---- key-block list ----
    const bool full = (i == 0 || i == NB - 1);
    int nt;
    int kbl[8], mtl[8], mpl[8];
    if (full) {
        nt = NB;
    } else {
        const int* ra = rand_attn + ((size_t)bh * (NB - 2) + (i - 1)) * 3;
        int r0 = __ldg(ra + 0), r1 = __ldg(ra + 1), r2 = __ldg(ra + 2);
        if (i == 1) {
            kbl[0]=0; kbl[1]=1; kbl[2]=2; kbl[3]=NB-1;
            mtl[0]=mtl[1]=mtl[2]=mtl[3]=0; mpl[0]=mpl[1]=mpl[2]=mpl[3]=0;
            kbl[4]=r0; kbl[5]=r1; kbl[6]=r2;
            mtl[4]=mtl[5]=mtl[6]=2; mpl[4]=0; mpl[5]=1; mpl[6]=2;
            nt = 7;
        } else if (i == NB - 2) {
            kbl[0]=0; kbl[1]=NB-3; kbl[2]=NB-2; kbl[3]=NB-1;
            mtl[0]=mtl[1]=mtl[2]=mtl[3]=0; mpl[0]=mpl[1]=mpl[2]=mpl[3]=0;
            kbl[4]=r0; kbl[5]=r1; kbl[6]=r2;
            mtl[4]=mtl[5]=mtl[6]=2; mpl[4]=0; mpl[5]=1; mpl[6]=2;
            nt = 7;
        } else {
            kbl[0]=0;    mtl[0]=0; mpl[0]=0;
            kbl[1]=i-1;  mtl[1]=1; mpl[1]=0;
            kbl[2]=i;    mtl[2]=1; mpl[2]=1;
            kbl[3]=i+1;  mtl[3]=1; mpl[3]=2;
            kbl[4]=r0;   mtl[4]=2; mpl[4]=0;
            kbl[5]=r1;   mtl[5]=2; mpl[5]=1;
            kbl[6]=r2;   mtl[6]=2; mpl[6]=2;
            kbl[7]=NB-1; mtl[7]=0; mpl[7]=0;
            nt = 8;
        }
    }

    // ---- packed accumulators: dims [4jg,4jg+4) and [32+4jg,+4) as 4 f32x2 pairs ----
    u64 acc2[4][4];
    float mrow[4], lrow[4];
    #pragma unroll
    for (int r = 0; r < 4; r++) {
        mrow[r] = -1e30f; lrow[r] = 0.0f;
        #pragma unroll
        for (int p = 0; p < 4; p++) acc2[r][p] = 0ull;
    }

    for (int t = 0; t < nt; t++) {
        int kb, mt, mp;
        if (full) { kb = t; mt = 0; mp = 0; }
        else      { kb = kbl[t]; mt = mtl[t]; mp = mpl[t]; }

        __syncthreads();

        // ---- load K, V tile ----
        const float* Kg = K + ((size_t)bh * SEQL + (size_t)kb * 64) * DIM;
        const float* Vg = V + ((size_t)bh * SEQL + (size_t)kb * 64) * DIM;
        for (int f = tid; f < 1024; f += 128) {
            int row = f >> 4, c4 = (f & 15) << 2;
            float4 kk = __ldg((const float4*)(Kg + row * DIM + c4));
            *(float4*)(Ks + row * PK + c4) = kk;
            float4 vv = __ldg((const float4*)(Vg + row * DIM + c4));
            *(float4*)(Vs + row * PVV + c4) = vv;
        }
        __syncthreads();

        // ---- QK^T with f32x2, paired over d ----
        u64 s2[4][8];
        #pragma unroll
        for (int r = 0; r < 4; r++)
            #pragma unroll
            for (int c = 0; c < 8; c++) s2[r][c] = 0ull;

        #pragma unroll 4
        for (int d4 = 0; d4 < 16; d4++) {
            ulonglong2 qv[4], kv[8];
            #pragma unroll
            for (int r = 0; r < 4; r++)
                qv[r] = *(const ulonglong2*)(const void*)(Qs + (q0 + r) * PQ + (d4 << 2));
            #pragma unroll
            for (int c = 0; c < 8; c++)
                kv[c] = *(const ulonglong2*)(const void*)(Ks + (jg + (c << 3)) * PK + (d4 << 2));
            #pragma unroll
            for (int r = 0; r < 4; r++)
                #pragma unroll
                for (int c = 0; c < 8; c++) {
                    s2[r][c] = ffma2(qv[r].x, kv[c].x, s2[r][c]);
                    s2[r][c] = ffma2(qv[r].y, kv[c].y, s2[r][c]);
                }
        }

        // reduce packed pairs -> scalar scores (Q was pre-scaled)
        float s[4][8];
        #pragma unroll
        for (int r = 0; r < 4; r++)
            #pragma unroll
            for (int c = 0; c < 8; c++) {
                float2 u = unpack2(s2[r][c]);
                s[r][c] = u.x + u.y;
            }

        // ---- mask ----
        if (mt == 0) {
            const float* tmp = to_mask + (size_t)b * SEQL + (size_t)kb * 64 + jg;
            float tadd[8];
            #pragma unroll
            for (int c = 0; c < 8; c++)
                tadd[c] = (1.0f - __ldg(tmp + (c << 3))) * NEG;
            #pragma unroll
            for (int r = 0; r < 4; r++)
                #pragma unroll
                for (int c = 0; c < 8; c++)
                    s[r][c] += tadd[c];
        } else if (mt == 1) {
            const float* bm = band_mask
                + (((size_t)b * (NB - 4) + (i - 2)) * 64) * 192 + mp * 64 + jg;
            #pragma unroll
            for (int r = 0; r < 4; r++) {
                const float* bmr = bm + (size_t)(q0 + r) * 192;
                #pragma unroll
                for (int c = 0; c < 8; c++)
                    s[r][c] += (1.0f - __ldg(bmr + (c << 3))) * NEG;
            }
        } else {
            const float* rm = rand_mask
                + (((size_t)bh * (NB - 2) + (i - 1)) * 64) * 192 + mp * 64 + jg;
            #pragma unroll
            for (int r = 0; r < 4; r++) {
                const float* rmr = rm + (size_t)(q0 + r) * 192;
                #pragma unroll
                for (int c = 0; c < 8; c++)
                    s[r][c] += (1.0f - __ldg(rmr + (c << 3))) * NEG;
            }
        }

        // ---- online softmax ----
        #pragma unroll
        for (int r = 0; r < 4; r++) {
            float mx = s[r][0];
            #pragma unroll
            for (int c = 1; c < 8; c++) mx = fmaxf(mx, s[r][c]);
            mx = fmaxf(mx, __shfl_xor_sync(0xffffffffu, mx, 1));
            mx = fmaxf(mx, __shfl_xor_sync(0xffffffffu, mx, 2));
            mx = fmaxf(mx, __shfl_xor_sync(0xffffffffu, mx, 4));
            float mnew = fmaxf(mrow[r], mx);
            float corr = __expf(mrow[r] - mnew);
            float ls = 0.0f;
            #pragma unroll
            for (int c = 0; c < 8; c++) {
                float p = __expf(s[r][c] - mnew);
                s[r][c] = p;
                ls += p;
            }
            ls += __shfl_xor_sync(0xffffffffu, ls, 1);
            ls += __shfl_xor_sync(0xffffffffu, ls, 2);
            ls += __shfl_xor_sync(0xffffffffu, ls, 4);
            lrow[r] = lrow[r] * corr + ls;
            mrow[r] = mnew;
            u64 corr2 = splat2(corr);
            #pragma unroll
            for (int p = 0; p < 4; p++) acc2[r][p] = fmul2(acc2[r][p], corr2);
            #pragma unroll
            for (int c = 0; c < 8; c++)
                Ps[(q0 + r) * PQ + jg + (c << 3)] = s[r][c];
        }
        __syncthreads();

        // ---- PV with f32x2, paired over output dims ----
        #pragma unroll 4
        for (int j4 = 0; j4 < 16; j4++) {
            float4 pv[4];
            #pragma unroll
            for (int r = 0; r < 4; r++)
                pv[r] = *(const float4*)(Ps + (q0 + r) * PQ + (j4 << 2));
            ulonglong2 va[4], vb[4];
            #pragma unroll
            for (int jj = 0; jj < 4; jj++) {
                const float* vrow = Vs + ((j4 << 2) + jj) * PVV;
                va[jj] = *(const ulonglong2*)(const void*)(vrow + (jg << 2));
                vb[jj] = *(const ulonglong2*)(const void*)(vrow + 32 + (jg << 2));
            }
            #pragma unroll
            for (int r = 0; r < 4; r++) {
                float pr[4] = { pv[r].x, pv[r].y, pv[r].z, pv[r].w };
                #pragma unroll
                for (int jj = 0; jj < 4; jj++) {
                    u64 p2 = splat2(pr[jj]);
                    acc2[r][0] = ffma2(p2, va[jj].x, acc2[r][0]);
                    acc2[r][1] = ffma2(p2, va[jj].y, acc2[r][1]);
                    acc2[r][2] = ffma2(p2, vb[jj].x, acc2[r][2]);
                    acc2[r][3] = ffma2(p2, vb[jj].y, acc2[r][3]);
                }
            }
        }
    }

    // ---- epilogue ----
    float* og = out + ((size_t)bh * SEQL + (size_t)i * 64) * DIM;
    #pragma unroll
    for (int r = 0; r < 4; r++) {
        float fm = __ldg(from_mask + (size_t)b * SEQL + (size_t)i * 64 + q0 + r);
        float inv = fm / lrow[r];
        float2 a0 = unpack2(acc2[r][0]);
        float2 a1 = unpack2(acc2[r][1]);
        float2 b0 = unpack2(acc2[r][2]);
        float2 b1 = unpack2(acc2[r][3]);
        float4 oa = make_float4(a0.x*inv, a0.y*inv, a1.x*inv, a1.y*inv);
        float4 ob = make_float4(b0.x*inv, b0.y*inv, b1.x*inv, b1.y*inv);
        *(float4*)(og + (q0 + r) * DIM + (jg << 2))      = oa;
        *(float4*)(og + (q0 + r) * DIM + 32 + (jg << 2)) = ob;
    }
}

extern "C" void kernel_launch(void* const* d_in, const int* in_sizes, int n_in,
                              void* d_out, int out_size)
{
    const float* Q  = (const float*)d_in[0];
    const float* K  = (const float*)d_in[1];
    const float* V  = (const float*)d_in[2];
    const int*   RA = (const int*)  d_in[3];
    const float* FM = (const float*)d_in[4];
    const float* TM = (const float*)d_in[5];
    const float* RM = (const float*)d_in[6];
    const float* BM = (const float*)d_in[7];
    float* O = (float*)d_out;

    cudaFuncSetAttribute(bb_attn_kernel,
                         cudaFuncAttributeMaxDynamicSharedMemorySize, SMEM_BYTES);

    dim3 grid(2 * 16 * NB);
    bb_attn_kernel<<<grid, 128, SMEM_BYTES>>>(Q, K, V, RA, FM, TM, RM, BM, O);
}